// round 9
// baseline (speedup 1.0000x reference)
#include <cuda_runtime.h>
#include <cuda_fp16.h>

// ---------------------------------------------------------------------------
// GAT (2-layer, PyG-style) on B200 (sm_100a). Pristine module form; total
// __device__ data ~12.2 MB (below the driver's module-chunk threshold).
//
// Key algebraic restructuring: layer-2 GEMM commutes with the segment-sum:
//     out[d] = (sum_e coef_e * hin[src_e]) @ W2 + b2
//     a_s2[i] = hin[i] . (W2 @ att_src2),  a_d2[i] = hin[i] . (W2 @ att_dst2)
// so h2 (12.8 MB) and the second GEMM are never materialized.
//
// Pipeline:
//   1) CSR build over dst (int atomics; src as uint16)
//   2) gemm1: h1 = x @ W1 (fp32)        -> d_out
//   3) att1 : (as1, ad1) packed half2   -> g_a1
//   4) edge1: softmax-agg + b1 + ELU    -> g_hin (fp16)      [reads d_out]
//   5) vs/vd: W2 @ att2 vectors         -> g_vs/g_vd
//   6) att2 : as2/ad2 = hin . vs/vd     -> g_as2/g_ad2 (fp32)
//   7) edge2: softmax-agg over hin, then fused @W2 + b2 + log_softmax
//             -> d_out (h1 dead)
// Self-loops handled analytically. Zero local memory in every kernel.
// ---------------------------------------------------------------------------

#define NNODES 50000
#define NEDGES 1600000
#define SLOPE  0.2f
#define EPSV   1e-16f

// ------------------------- scratch (static device) --------------------------
__device__ unsigned short g_csr[NEDGES];        // 3.2 MB
__device__ __half2        g_a1[NNODES * 8];     // (as,ad) per head, 1.6 MB
__device__ __half2        g_hin[NNODES * 32];   // hin fp16 [N,64], 6.4 MB
__device__ float          g_as2[NNODES];        // 0.2 MB
__device__ float          g_ad2[NNODES];        // 0.2 MB
__device__ int            g_row_ptr[NNODES + 1];
__device__ int            g_deg[NNODES];
__device__ int            g_pos[NNODES];
__device__ int            g_bsum[64];
__device__ int            g_boff[64];
__device__ float          g_vs[64];
__device__ float          g_vd[64];

__device__ __forceinline__ float lrelu(float v) { return fmaxf(v, SLOPE * v); }

// ------------------------------ CSR build -----------------------------------
__global__ void __launch_bounds__(256) k_init_deg(int n) {
    int i = blockIdx.x * blockDim.x + threadIdx.x;
    if (i < n) g_deg[i] = 0;
}

__global__ void __launch_bounds__(256) k_count(const int* __restrict__ dst, int n) {
    int e = blockIdx.x * blockDim.x + threadIdx.x;
    if (e < n) atomicAdd(&g_deg[dst[e]], 1);
}

#define SCAN_B 1024
__global__ void __launch_bounds__(SCAN_B) k_scan_local(int n) {
    __shared__ int s[SCAN_B];
    int tid = threadIdx.x;
    int i = blockIdx.x * SCAN_B + tid;
    int v = (i < n) ? g_deg[i] : 0;
    s[tid] = v;
    __syncthreads();
#pragma unroll
    for (int off = 1; off < SCAN_B; off <<= 1) {
        int t = (tid >= off) ? s[tid - off] : 0;
        __syncthreads();
        s[tid] += t;
        __syncthreads();
    }
    if (i < n) g_row_ptr[i] = s[tid] - v;
    if (tid == SCAN_B - 1) g_bsum[blockIdx.x] = s[tid];
}

__global__ void __launch_bounds__(32) k_scan_block(int nblk) {
    if (threadIdx.x == 0 && blockIdx.x == 0) {
        int off = 0;
        for (int b = 0; b < nblk; b++) { int t = g_bsum[b]; g_boff[b] = off; off += t; }
    }
}

__global__ void __launch_bounds__(SCAN_B) k_scan_add(int n) {
    int tid = threadIdx.x;
    int i = blockIdx.x * SCAN_B + tid;
    if (i < n) {
        int r = g_row_ptr[i] + g_boff[blockIdx.x];
        g_row_ptr[i] = r;
        g_pos[i] = r;
    }
    if (i == 0) g_row_ptr[NNODES] = NEDGES;
}

__global__ void __launch_bounds__(256) k_scatter(const int* __restrict__ src,
                                                 const int* __restrict__ dst, int n) {
    int e = blockIdx.x * blockDim.x + threadIdx.x;
    if (e < n) {
        int d = dst[e];
        int p = atomicAdd(&g_pos[d], 1);
        g_csr[p] = (unsigned short)src[e];
    }
}

// ------------------------------- GEMM1 --------------------------------------
// C[M,64] = A[M,256] @ B[256,64], fp32, tile 128x64, BK=16, 256 threads.
__global__ void __launch_bounds__(256) k_gemm1(const float* __restrict__ A,
                                               const float* __restrict__ B,
                                               float* __restrict__ C, int M) {
    const int block_row = blockIdx.x * 128;
    if (block_row >= M) return;
    __shared__ float xs[128][17];
    __shared__ float ws[16][64];
    const int tid = threadIdx.x;
    const int colbase = (tid & 15) * 4;
    const int rowbase = tid >> 4;
    float acc[8][4];
#pragma unroll
    for (int i = 0; i < 8; i++)
#pragma unroll
        for (int j = 0; j < 4; j++) acc[i][j] = 0.f;

    for (int k0 = 0; k0 < 256; k0 += 16) {
#pragma unroll
        for (int it = 0; it < 2; it++) {
            int f4 = tid + it * 256;
            int r = f4 >> 2;
            int c = (f4 & 3) * 4;
            int gr = block_row + r;
            float4 v = make_float4(0.f, 0.f, 0.f, 0.f);
            if (gr < M) v = *(const float4*)(A + (size_t)gr * 256 + k0 + c);
            xs[r][c + 0] = v.x; xs[r][c + 1] = v.y;
            xs[r][c + 2] = v.z; xs[r][c + 3] = v.w;
        }
        {
            int r = tid >> 4;
            int c = (tid & 15) * 4;
            *(float4*)&ws[r][c] = *(const float4*)(B + (size_t)(k0 + r) * 64 + c);
        }
        __syncthreads();
#pragma unroll
        for (int kk = 0; kk < 16; kk++) {
            float b0 = ws[kk][colbase + 0];
            float b1 = ws[kk][colbase + 1];
            float b2 = ws[kk][colbase + 2];
            float b3 = ws[kk][colbase + 3];
#pragma unroll
            for (int i = 0; i < 8; i++) {
                float a = xs[rowbase + i * 16][kk];
                acc[i][0] += a * b0;
                acc[i][1] += a * b1;
                acc[i][2] += a * b2;
                acc[i][3] += a * b3;
            }
        }
        __syncthreads();
    }
#pragma unroll
    for (int i = 0; i < 8; i++) {
        int gr = block_row + rowbase + i * 16;
        if (gr < M)
            *(float4*)(C + (size_t)gr * 64 + colbase) =
                make_float4(acc[i][0], acc[i][1], acc[i][2], acc[i][3]);
    }
}

// --------------------------- attention dots (L1) -----------------------------
__global__ void __launch_bounds__(256) k_att1(const float* __restrict__ h1,
                                              const float* __restrict__ att_src,
                                              const float* __restrict__ att_dst, int n) {
    __shared__ float ss[64], sd[64];
    int tid = threadIdx.x;
    if (tid < 64) { ss[tid] = att_src[tid]; sd[tid] = att_dst[tid]; }
    __syncthreads();
    int i = blockIdx.x * blockDim.x + tid;
    if (i >= n) return;
    const float* h = h1 + (size_t)i * 64;
    float as[8], ad[8];
#pragma unroll
    for (int hh = 0; hh < 8; hh++) { as[hh] = 0.f; ad[hh] = 0.f; }
#pragma unroll
    for (int c = 0; c < 16; c++) {
        float4 v = *(const float4*)(h + c * 4);
        const int base = c * 4;
        const int head0 = base >> 3;          // constant per unrolled iteration
        as[head0] += v.x * ss[base] + v.y * ss[base + 1] + v.z * ss[base + 2] + v.w * ss[base + 3];
        ad[head0] += v.x * sd[base] + v.y * sd[base + 1] + v.z * sd[base + 2] + v.w * sd[base + 3];
    }
#pragma unroll
    for (int hh = 0; hh < 8; hh++)
        g_a1[(size_t)i * 8 + hh] = __floats2half2_rn(as[hh], ad[hh]);
}

// --------------------- layer 1: fused softmax + aggregate -------------------
// warp per node; lane owns features 2*lane, 2*lane+1 (same head = lane>>2).
__global__ void __launch_bounds__(256) k_edge1(const float* __restrict__ h1,
                                               const float* __restrict__ b1, int n) {
    int wid = (blockIdx.x * blockDim.x + threadIdx.x) >> 5;
    int lane = threadIdx.x & 31;
    if (wid >= n) return;
    const int d = wid;
    const int beg = g_row_ptr[d];
    const int end = g_row_ptr[d + 1];

    float ad[8], asf[8];
#pragma unroll
    for (int h = 0; h < 8; h++) {
        float2 p = __half22float2(g_a1[(size_t)d * 8 + h]);
        asf[h] = p.x; ad[h] = p.y;
    }
    float aself[8], m[8];
#pragma unroll
    for (int h = 0; h < 8; h++) { aself[h] = lrelu(asf[h] + ad[h]); m[h] = aself[h]; }

    // phase 1: max
    for (int e = beg + lane; e < end; e += 32) {
        int s = g_csr[e];
        const __half2* pa = g_a1 + (size_t)s * 8;
#pragma unroll
        for (int h = 0; h < 8; h++) {
            float2 p = __half22float2(pa[h]);
            m[h] = fmaxf(m[h], lrelu(p.x + ad[h]));
        }
    }
#pragma unroll
    for (int off = 16; off; off >>= 1)
#pragma unroll
        for (int h = 0; h < 8; h++)
            m[h] = fmaxf(m[h], __shfl_xor_sync(0xffffffffu, m[h], off));

    // phase 2: sum of exp
    float sm[8];
#pragma unroll
    for (int h = 0; h < 8; h++) sm[h] = 0.f;
    for (int e = beg + lane; e < end; e += 32) {
        int s = g_csr[e];
        const __half2* pa = g_a1 + (size_t)s * 8;
#pragma unroll
        for (int h = 0; h < 8; h++) {
            float2 p = __half22float2(pa[h]);
            sm[h] += __expf(lrelu(p.x + ad[h]) - m[h]);
        }
    }
#pragma unroll
    for (int off = 16; off; off >>= 1)
#pragma unroll
        for (int h = 0; h < 8; h++) sm[h] += __shfl_xor_sync(0xffffffffu, sm[h], off);
    float rden[8];
#pragma unroll
    for (int h = 0; h < 8; h++)
        rden[h] = 1.f / (sm[h] + __expf(aself[h] - m[h]) + EPSV);

    // per-lane head constants via unrolled predicated selects (no local mem)
    const int h0 = lane >> 2;                 // features 2*lane, 2*lane+1 share head
    float ad_h = ad[0], m_h = m[0], rd_h = rden[0], asf_h = aself[0];
#pragma unroll
    for (int h = 1; h < 8; h++) {
        if (h0 == h) { ad_h = ad[h]; m_h = m[h]; rd_h = rden[h]; asf_h = aself[h]; }
    }

    // phase 3: aggregate
    const int f0 = 2 * lane;
    float acc0 = 0.f, acc1 = 0.f;
    for (int e = beg; e < end; e++) {
        int s = g_csr[e];
        float2 p = __half22float2(g_a1[(size_t)s * 8 + h0]);
        float w = __expf(lrelu(p.x + ad_h) - m_h) * rd_h;
        float2 hv = *(const float2*)(h1 + (size_t)s * 64 + f0);
        acc0 += hv.x * w;
        acc1 += hv.y * w;
    }
    {   // self loop
        float w = __expf(asf_h - m_h) * rd_h;
        float2 hv = *(const float2*)(h1 + (size_t)d * 64 + f0);
        acc0 += hv.x * w;
        acc1 += hv.y * w;
    }
    float v0 = acc0 + b1[f0];
    float v1 = acc1 + b1[f0 + 1];
    v0 = (v0 > 0.f) ? v0 : (__expf(v0) - 1.f);   // ELU
    v1 = (v1 > 0.f) ? v1 : (__expf(v1) - 1.f);
    g_hin[(size_t)d * 32 + lane] = __floats2half2_rn(v0, v1);
}

// ---------------- vs = W2 @ att_src2, vd = W2 @ att_dst2 --------------------
__global__ void __launch_bounds__(64) k_vs(const float* __restrict__ W2,
                                           const float* __restrict__ att_src2,
                                           const float* __restrict__ att_dst2) {
    int k = threadIdx.x;   // 0..63
    float vs = 0.f, vd = 0.f;
    for (int j = 0; j < 64; j++) {
        float w = W2[k * 64 + j];
        vs += w * att_src2[j];
        vd += w * att_dst2[j];
    }
    g_vs[k] = vs;
    g_vd[k] = vd;
}

// --------------------- layer-2 attention dots from hin -----------------------
__global__ void __launch_bounds__(256) k_att2(int n) {
    __shared__ float svs[64], svd[64];
    int tid = threadIdx.x;
    if (tid < 64) { svs[tid] = g_vs[tid]; svd[tid] = g_vd[tid]; }
    __syncthreads();
    int i = blockIdx.x * blockDim.x + tid;
    if (i >= n) return;
    const __half2* ph = g_hin + (size_t)i * 32;
    float as = 0.f, adv = 0.f;
#pragma unroll
    for (int c = 0; c < 32; c++) {
        float2 f = __half22float2(ph[c]);
        as  += f.x * svs[2 * c] + f.y * svs[2 * c + 1];
        adv += f.x * svd[2 * c] + f.y * svd[2 * c + 1];
    }
    g_as2[i] = as;
    g_ad2[i] = adv;
}

// ---- layer 2: softmax-agg over hin, fused @W2 + b2 + log_softmax -> out -----
__global__ void __launch_bounds__(256) k_edge2(const float* __restrict__ W2,
                                               const float* __restrict__ b2,
                                               float* __restrict__ out, int n) {
    __shared__ float2 W2s[64 * 32];          // W2 as float2 pairs [k][lane]
    __shared__ float  b2s[64];
    __shared__ float  sagg[8][64];
    int tid = threadIdx.x;
    {
        const float2* w2v = (const float2*)W2;
#pragma unroll
        for (int it = 0; it < 8; it++) W2s[tid + it * 256] = w2v[tid + it * 256];
        if (tid < 64) b2s[tid] = b2[tid];
    }
    __syncthreads();

    int wid = (blockIdx.x * blockDim.x + tid) >> 5;
    int wloc = (tid >> 5);
    int lane = tid & 31;
    if (wid >= n) return;
    const int d = wid;
    const int beg = g_row_ptr[d];
    const int end = g_row_ptr[d + 1];
    const float ad2 = g_ad2[d];
    const float aself = lrelu(g_as2[d] + ad2);

    float m = aself;
    for (int e = beg + lane; e < end; e += 32)
        m = fmaxf(m, lrelu(g_as2[g_csr[e]] + ad2));
#pragma unroll
    for (int off = 16; off; off >>= 1)
        m = fmaxf(m, __shfl_xor_sync(0xffffffffu, m, off));

    float sm = 0.f;
    for (int e = beg + lane; e < end; e += 32)
        sm += __expf(lrelu(g_as2[g_csr[e]] + ad2) - m);
#pragma unroll
    for (int off = 16; off; off >>= 1)
        sm += __shfl_xor_sync(0xffffffffu, sm, off);
    float rden = 1.f / (sm + __expf(aself - m) + EPSV);

    // aggregate hin (lane owns features 2*lane, 2*lane+1)
    float acc0 = 0.f, acc1 = 0.f;
    for (int e = beg; e < end; e++) {
        int s = g_csr[e];
        float w = __expf(lrelu(g_as2[s] + ad2) - m) * rden;
        float2 f = __half22float2(g_hin[(size_t)s * 32 + lane]);
        acc0 += f.x * w;
        acc1 += f.y * w;
    }
    {
        float w = __expf(aself - m) * rden;
        float2 f = __half22float2(g_hin[(size_t)d * 32 + lane]);
        acc0 += f.x * w;
        acc1 += f.y * w;
    }

    // stage agg, then fused @W2 + b2
    sagg[wloc][2 * lane]     = acc0;
    sagg[wloc][2 * lane + 1] = acc1;
    __syncwarp();
    float o0 = b2s[2 * lane];
    float o1 = b2s[2 * lane + 1];
#pragma unroll
    for (int k = 0; k < 64; k++) {
        float a = sagg[wloc][k];
        float2 w2 = W2s[k * 32 + lane];
        o0 += a * w2.x;
        o1 += a * w2.y;
    }

    // log_softmax over the 64 outputs held by this warp
    float mx = fmaxf(o0, o1);
#pragma unroll
    for (int off = 16; off; off >>= 1)
        mx = fmaxf(mx, __shfl_xor_sync(0xffffffffu, mx, off));
    float se = __expf(o0 - mx) + __expf(o1 - mx);
#pragma unroll
    for (int off = 16; off; off >>= 1)
        se += __shfl_xor_sync(0xffffffffu, se, off);
    float l = mx + logf(se);
    float2* out2 = (float2*)(out + (size_t)d * 64);
    out2[lane] = make_float2(o0 - l, o1 - l);
}

// ------------------------------ launcher ------------------------------------
extern "C" void kernel_launch(void* const* d_in, const int* in_sizes, int n_in,
                              void* d_out, int out_size) {
    const float* x        = (const float*)d_in[0];
    const int*   ei       = (const int*)d_in[1];
    const float* W1       = (const float*)d_in[2];
    const float* att_src1 = (const float*)d_in[3];
    const float* att_dst1 = (const float*)d_in[4];
    const float* b1       = (const float*)d_in[5];
    const float* W2       = (const float*)d_in[6];
    const float* att_src2 = (const float*)d_in[7];
    const float* att_dst2 = (const float*)d_in[8];
    const float* b2       = (const float*)d_in[9];
    float* out = (float*)d_out;

    const int* src = ei;
    const int* dst = ei + NEDGES;

    const int nblk_scan = (NNODES + SCAN_B - 1) / SCAN_B;   // 49

    // CSR build
    k_init_deg<<<(NNODES + 255) / 256, 256>>>(NNODES);
    k_count<<<(NEDGES + 255) / 256, 256>>>(dst, NEDGES);
    k_scan_local<<<nblk_scan, SCAN_B>>>(NNODES);
    k_scan_block<<<1, 32>>>(nblk_scan);
    k_scan_add<<<nblk_scan, SCAN_B>>>(NNODES);
    k_scatter<<<(NEDGES + 255) / 256, 256>>>(src, dst, NEDGES);

    // layer 1: h1 -> d_out, logits -> g_a1, hin(fp16) -> g_hin
    k_gemm1<<<(NNODES + 127) / 128, 256>>>(x, W1, out, NNODES);
    k_att1<<<(NNODES + 255) / 256, 256>>>(out, att_src1, att_dst1, NNODES);
    k_edge1<<<(NNODES * 32 + 255) / 256, 256>>>(out, b1, NNODES);

    // layer 2 (no GEMM2: folded into edge2 epilogue)
    k_vs<<<1, 64>>>(W2, att_src2, att_dst2);
    k_att2<<<(NNODES + 255) / 256, 256>>>(NNODES);
    k_edge2<<<(NNODES * 32 + 255) / 256, 256>>>(W2, b2, out, NNODES);
}

// round 12
// speedup vs baseline: 1.2739x; 1.2739x over previous
#include <cuda_runtime.h>
#include <cuda_fp16.h>

// ---------------------------------------------------------------------------
// GAT (2-layer, PyG-style) on B200 (sm_100a). Pristine module form; total
// __device__ data ~12.2 MB (fits pre-mapped context memory => no checkpoint
// delta). Layer-2 GEMM is folded through the segment-sum (h2 never exists).
//
// R10/R11/R12: max-free single-pass softmax-aggregate in both edge kernels
// (exact softmax shift-invariance; logits << 88 so no overflow), att2 fused
// into edge1 epilogue, warp-parallel block-offset scan.
// (R12 = R10 resubmitted verbatim after two infra-only bench failures.)
//
// Pipeline:
//   1) CSR build over dst (int atomics; src as uint16)
//   2) gemm1: h1 = x @ W1 (fp32)            -> d_out
//   3) att1 : (as1, ad1) packed half2       -> g_a1
//   4) vs/vd: W2 @ att2 vectors             -> g_vs/g_vd
//   5) edge1: ONE-pass softmax-agg + b1 + ELU -> g_hin (fp16),
//             fused as2/ad2 = hin.(vs/vd)   -> g_as2/g_ad2
//   6) edge2: ONE-pass softmax-agg over hin, fused @W2 + b2 + log_softmax
//             -> d_out (h1 dead)
// Self-loops handled analytically. Zero local memory in every kernel.
// ---------------------------------------------------------------------------

#define NNODES 50000
#define NEDGES 1600000
#define SLOPE  0.2f
#define EPSV   1e-16f

// ------------------------- scratch (static device) --------------------------
__device__ unsigned short g_csr[NEDGES];        // 3.2 MB
__device__ __half2        g_a1[NNODES * 8];     // (as,ad) per head, 1.6 MB
__device__ __half2        g_hin[NNODES * 32];   // hin fp16 [N,64], 6.4 MB
__device__ float          g_as2[NNODES];        // 0.2 MB
__device__ float          g_ad2[NNODES];        // 0.2 MB
__device__ int            g_row_ptr[NNODES + 1];
__device__ int            g_deg[NNODES];
__device__ int            g_pos[NNODES];
__device__ int            g_bsum[64];
__device__ int            g_boff[64];
__device__ float          g_vs[64];
__device__ float          g_vd[64];

__device__ __forceinline__ float lrelu(float v) { return fmaxf(v, SLOPE * v); }

// ------------------------------ CSR build -----------------------------------
__global__ void __launch_bounds__(256) k_init_deg(int n) {
    int i = blockIdx.x * blockDim.x + threadIdx.x;
    if (i < n) g_deg[i] = 0;
}

__global__ void __launch_bounds__(256) k_count(const int* __restrict__ dst, int n) {
    int e = blockIdx.x * blockDim.x + threadIdx.x;
    if (e < n) atomicAdd(&g_deg[dst[e]], 1);
}

#define SCAN_B 1024
__global__ void __launch_bounds__(SCAN_B) k_scan_local(int n) {
    __shared__ int s[SCAN_B];
    int tid = threadIdx.x;
    int i = blockIdx.x * SCAN_B + tid;
    int v = (i < n) ? g_deg[i] : 0;
    s[tid] = v;
    __syncthreads();
#pragma unroll
    for (int off = 1; off < SCAN_B; off <<= 1) {
        int t = (tid >= off) ? s[tid - off] : 0;
        __syncthreads();
        s[tid] += t;
        __syncthreads();
    }
    if (i < n) g_row_ptr[i] = s[tid] - v;
    if (tid == SCAN_B - 1) g_bsum[blockIdx.x] = s[tid];
}

// warp-parallel scan over <=64 block sums (was a 1-thread serial loop, ~6us)
__global__ void __launch_bounds__(64) k_scan_block(int nblk) {
    __shared__ int s[64];
    int i = threadIdx.x;
    int v = (i < nblk) ? g_bsum[i] : 0;
    s[i] = v;
    __syncthreads();
#pragma unroll
    for (int off = 1; off < 64; off <<= 1) {
        int t = (i >= off) ? s[i - off] : 0;
        __syncthreads();
        s[i] += t;
        __syncthreads();
    }
    if (i < nblk) g_boff[i] = s[i] - v;
}

__global__ void __launch_bounds__(SCAN_B) k_scan_add(int n) {
    int tid = threadIdx.x;
    int i = blockIdx.x * SCAN_B + tid;
    if (i < n) {
        int r = g_row_ptr[i] + g_boff[blockIdx.x];
        g_row_ptr[i] = r;
        g_pos[i] = r;
    }
    if (i == 0) g_row_ptr[NNODES] = NEDGES;
}

__global__ void __launch_bounds__(256) k_scatter(const int* __restrict__ src,
                                                 const int* __restrict__ dst, int n) {
    int e = blockIdx.x * blockDim.x + threadIdx.x;
    if (e < n) {
        int d = dst[e];
        int p = atomicAdd(&g_pos[d], 1);
        g_csr[p] = (unsigned short)src[e];
    }
}

// ------------------------------- GEMM1 --------------------------------------
// C[M,64] = A[M,256] @ B[256,64], fp32, tile 128x64, BK=16, 256 threads.
__global__ void __launch_bounds__(256) k_gemm1(const float* __restrict__ A,
                                               const float* __restrict__ B,
                                               float* __restrict__ C, int M) {
    const int block_row = blockIdx.x * 128;
    if (block_row >= M) return;
    __shared__ float xs[128][17];
    __shared__ float ws[16][64];
    const int tid = threadIdx.x;
    const int colbase = (tid & 15) * 4;
    const int rowbase = tid >> 4;
    float acc[8][4];
#pragma unroll
    for (int i = 0; i < 8; i++)
#pragma unroll
        for (int j = 0; j < 4; j++) acc[i][j] = 0.f;

    for (int k0 = 0; k0 < 256; k0 += 16) {
#pragma unroll
        for (int it = 0; it < 2; it++) {
            int f4 = tid + it * 256;
            int r = f4 >> 2;
            int c = (f4 & 3) * 4;
            int gr = block_row + r;
            float4 v = make_float4(0.f, 0.f, 0.f, 0.f);
            if (gr < M) v = *(const float4*)(A + (size_t)gr * 256 + k0 + c);
            xs[r][c + 0] = v.x; xs[r][c + 1] = v.y;
            xs[r][c + 2] = v.z; xs[r][c + 3] = v.w;
        }
        {
            int r = tid >> 4;
            int c = (tid & 15) * 4;
            *(float4*)&ws[r][c] = *(const float4*)(B + (size_t)(k0 + r) * 64 + c);
        }
        __syncthreads();
#pragma unroll
        for (int kk = 0; kk < 16; kk++) {
            float b0 = ws[kk][colbase + 0];
            float b1 = ws[kk][colbase + 1];
            float b2 = ws[kk][colbase + 2];
            float b3 = ws[kk][colbase + 3];
#pragma unroll
            for (int i = 0; i < 8; i++) {
                float a = xs[rowbase + i * 16][kk];
                acc[i][0] += a * b0;
                acc[i][1] += a * b1;
                acc[i][2] += a * b2;
                acc[i][3] += a * b3;
            }
        }
        __syncthreads();
    }
#pragma unroll
    for (int i = 0; i < 8; i++) {
        int gr = block_row + rowbase + i * 16;
        if (gr < M)
            *(float4*)(C + (size_t)gr * 64 + colbase) =
                make_float4(acc[i][0], acc[i][1], acc[i][2], acc[i][3]);
    }
}

// --------------------------- attention dots (L1) -----------------------------
__global__ void __launch_bounds__(256) k_att1(const float* __restrict__ h1,
                                              const float* __restrict__ att_src,
                                              const float* __restrict__ att_dst, int n) {
    __shared__ float ss[64], sd[64];
    int tid = threadIdx.x;
    if (tid < 64) { ss[tid] = att_src[tid]; sd[tid] = att_dst[tid]; }
    __syncthreads();
    int i = blockIdx.x * blockDim.x + tid;
    if (i >= n) return;
    const float* h = h1 + (size_t)i * 64;
    float as[8], ad[8];
#pragma unroll
    for (int hh = 0; hh < 8; hh++) { as[hh] = 0.f; ad[hh] = 0.f; }
#pragma unroll
    for (int c = 0; c < 16; c++) {
        float4 v = *(const float4*)(h + c * 4);
        const int base = c * 4;
        const int head0 = base >> 3;          // constant per unrolled iteration
        as[head0] += v.x * ss[base] + v.y * ss[base + 1] + v.z * ss[base + 2] + v.w * ss[base + 3];
        ad[head0] += v.x * sd[base] + v.y * sd[base + 1] + v.z * sd[base + 2] + v.w * sd[base + 3];
    }
#pragma unroll
    for (int hh = 0; hh < 8; hh++)
        g_a1[(size_t)i * 8 + hh] = __floats2half2_rn(as[hh], ad[hh]);
}

// ---------------- vs = W2 @ att_src2, vd = W2 @ att_dst2 --------------------
__global__ void __launch_bounds__(64) k_vs(const float* __restrict__ W2,
                                           const float* __restrict__ att_src2,
                                           const float* __restrict__ att_dst2) {
    int k = threadIdx.x;   // 0..63
    float vs = 0.f, vd = 0.f;
    for (int j = 0; j < 64; j++) {
        float w = W2[k * 64 + j];
        vs += w * att_src2[j];
        vd += w * att_dst2[j];
    }
    g_vs[k] = vs;
    g_vd[k] = vd;
}

// ------- layer 1: ONE-pass softmax-agg + ELU + fused layer-2 att dots -------
// warp per node; lane owns features 2*lane, 2*lane+1 (head = lane>>2).
// Max-free: coef = exp(a)/(sum exp(a)) is exactly the softmax (logits << 88).
__global__ void __launch_bounds__(256) k_edge1(const float* __restrict__ h1,
                                               const float* __restrict__ b1, int n) {
    int wid = (blockIdx.x * blockDim.x + threadIdx.x) >> 5;
    int lane = threadIdx.x & 31;
    if (wid >= n) return;
    const int d = wid;
    const int beg = g_row_ptr[d];
    const int end = g_row_ptr[d + 1];
    const int h0 = lane >> 2;
    const int f0 = 2 * lane;

    // dst-side logit pieces for this lane's head (global loads: no local mem)
    float2 pd = __half22float2(g_a1[(size_t)d * 8 + h0]);
    const float ad_h = pd.y;
    const float aself = lrelu(pd.x + ad_h);

    float acc0 = 0.f, acc1 = 0.f, sden = 0.f;
    for (int e = beg; e < end; e++) {
        int s = g_csr[e];
        float2 pa = __half22float2(g_a1[(size_t)s * 8 + h0]);
        float w = __expf(lrelu(pa.x + ad_h));
        sden += w;
        float2 hv = *(const float2*)(h1 + (size_t)s * 64 + f0);
        acc0 += hv.x * w;
        acc1 += hv.y * w;
    }
    {   // self loop
        float w = __expf(aself);
        sden += w;
        float2 hv = *(const float2*)(h1 + (size_t)d * 64 + f0);
        acc0 += hv.x * w;
        acc1 += hv.y * w;
    }
    float rinv = 1.f / (sden + EPSV);
    float v0 = acc0 * rinv + b1[f0];
    float v1 = acc1 * rinv + b1[f0 + 1];
    v0 = (v0 > 0.f) ? v0 : (__expf(v0) - 1.f);   // ELU
    v1 = (v1 > 0.f) ? v1 : (__expf(v1) - 1.f);
    g_hin[(size_t)d * 32 + lane] = __floats2half2_rn(v0, v1);

    // fused layer-2 attention dots: as2 = hin . vs, ad2 = hin . vd
    float ps = v0 * g_vs[f0] + v1 * g_vs[f0 + 1];
    float pdd = v0 * g_vd[f0] + v1 * g_vd[f0 + 1];
#pragma unroll
    for (int off = 16; off; off >>= 1) {
        ps  += __shfl_xor_sync(0xffffffffu, ps, off);
        pdd += __shfl_xor_sync(0xffffffffu, pdd, off);
    }
    if (lane == 0) {
        g_as2[d] = ps;
        g_ad2[d] = pdd;
    }
}

// -- layer 2: ONE-pass softmax-agg over hin, fused @W2 + b2 + log_softmax ----
__global__ void __launch_bounds__(256) k_edge2(const float* __restrict__ W2,
                                               const float* __restrict__ b2,
                                               float* __restrict__ out, int n) {
    __shared__ float2 W2s[64 * 32];          // W2 as float2 pairs [k][lane]
    __shared__ float  b2s[64];
    __shared__ float  sagg[8][64];
    int tid = threadIdx.x;
    {
        const float2* w2v = (const float2*)W2;
#pragma unroll
        for (int it = 0; it < 8; it++) W2s[tid + it * 256] = w2v[tid + it * 256];
        if (tid < 64) b2s[tid] = b2[tid];
    }
    __syncthreads();

    int wid = (blockIdx.x * blockDim.x + tid) >> 5;
    int wloc = (tid >> 5);
    int lane = tid & 31;
    if (wid >= n) return;
    const int d = wid;
    const int beg = g_row_ptr[d];
    const int end = g_row_ptr[d + 1];
    const float ad2 = g_ad2[d];
    const float aself = lrelu(g_as2[d] + ad2);

    float acc0 = 0.f, acc1 = 0.f, sden = 0.f;
    for (int e = beg; e < end; e++) {
        int s = g_csr[e];
        float w = __expf(lrelu(g_as2[s] + ad2));
        sden += w;
        float2 f = __half22float2(g_hin[(size_t)s * 32 + lane]);
        acc0 += f.x * w;
        acc1 += f.y * w;
    }
    {
        float w = __expf(aself);
        sden += w;
        float2 f = __half22float2(g_hin[(size_t)d * 32 + lane]);
        acc0 += f.x * w;
        acc1 += f.y * w;
    }
    float rinv = 1.f / (sden + EPSV);
    acc0 *= rinv;
    acc1 *= rinv;

    // stage agg, then fused @W2 + b2
    sagg[wloc][2 * lane]     = acc0;
    sagg[wloc][2 * lane + 1] = acc1;
    __syncwarp();
    float o0 = b2s[2 * lane];
    float o1 = b2s[2 * lane + 1];
#pragma unroll
    for (int k = 0; k < 64; k++) {
        float a = sagg[wloc][k];
        float2 w2 = W2s[k * 32 + lane];
        o0 += a * w2.x;
        o1 += a * w2.y;
    }

    // log_softmax over the 64 outputs held by this warp
    float mx = fmaxf(o0, o1);
#pragma unroll
    for (int off = 16; off; off >>= 1)
        mx = fmaxf(mx, __shfl_xor_sync(0xffffffffu, mx, off));
    float se = __expf(o0 - mx) + __expf(o1 - mx);
#pragma unroll
    for (int off = 16; off; off >>= 1)
        se += __shfl_xor_sync(0xffffffffu, se, off);
    float l = mx + logf(se);
    float2* out2 = (float2*)(out + (size_t)d * 64);
    out2[lane] = make_float2(o0 - l, o1 - l);
}

// ------------------------------ launcher ------------------------------------
extern "C" void kernel_launch(void* const* d_in, const int* in_sizes, int n_in,
                              void* d_out, int out_size) {
    const float* x        = (const float*)d_in[0];
    const int*   ei       = (const int*)d_in[1];
    const float* W1       = (const float*)d_in[2];
    const float* att_src1 = (const float*)d_in[3];
    const float* att_dst1 = (const float*)d_in[4];
    const float* b1       = (const float*)d_in[5];
    const float* W2       = (const float*)d_in[6];
    const float* att_src2 = (const float*)d_in[7];
    const float* att_dst2 = (const float*)d_in[8];
    const float* b2       = (const float*)d_in[9];
    float* out = (float*)d_out;

    const int* src = ei;
    const int* dst = ei + NEDGES;

    const int nblk_scan = (NNODES + SCAN_B - 1) / SCAN_B;   // 49

    // CSR build
    k_init_deg<<<(NNODES + 255) / 256, 256>>>(NNODES);
    k_count<<<(NEDGES + 255) / 256, 256>>>(dst, NEDGES);
    k_scan_local<<<nblk_scan, SCAN_B>>>(NNODES);
    k_scan_block<<<1, 64>>>(nblk_scan);
    k_scan_add<<<nblk_scan, SCAN_B>>>(NNODES);
    k_scatter<<<(NEDGES + 255) / 256, 256>>>(src, dst, NEDGES);

    // layer 1: h1 -> d_out, logits -> g_a1; vs/vd for fused att2
    k_gemm1<<<(NNODES + 127) / 128, 256>>>(x, W1, out, NNODES);
    k_att1<<<(NNODES + 255) / 256, 256>>>(out, att_src1, att_dst1, NNODES);
    k_vs<<<1, 64>>>(W2, att_src2, att_dst2);
    k_edge1<<<(NNODES * 32 + 255) / 256, 256>>>(out, b1, NNODES);

    // layer 2 (no GEMM2, no att2 kernel: both fused)
    k_edge2<<<(NNODES * 32 + 255) / 256, 256>>>(W2, b2, out, NNODES);
}

// round 13
// speedup vs baseline: 1.3038x; 1.0235x over previous
#include <cuda_runtime.h>
#include <cuda_fp16.h>

// ---------------------------------------------------------------------------
// GAT (2-layer, PyG-style) on B200 (sm_100a). Pristine module form; total
// __device__ data ~12.2 MB. Layer-2 GEMM folded through the segment-sum.
//
// R13 changes vs R12 (254 us):
//  * h1 stored fp16 in d_out (half2 [N,32]) -> edge1 gather traffic halved
//  * att1 fused into gemm1 epilogue (fp32-accurate dots, one kernel fewer)
//  * edge loops unrolled x4 with up-front index loads (4 independent
//    load chains -> better latency hiding)
//
// Pipeline:
//   1) CSR build over dst (int atomics; src as uint16)
//   2) gemm1: h1 = x @ W1 -> fp16 in d_out, fused att1 dots -> g_a1
//   3) vs/vd: W2 @ att2 vectors -> g_vs/g_vd
//   4) edge1: ONE-pass softmax-agg + b1 + ELU -> g_hin (fp16),
//             fused as2/ad2 = hin.(vs/vd) -> g_as2/g_ad2
//   5) edge2: ONE-pass softmax-agg over hin, fused @W2 + b2 + log_softmax
//             -> d_out (h1 dead)
// Self-loops handled analytically. Zero local memory in every kernel.
// ---------------------------------------------------------------------------

#define NNODES 50000
#define NEDGES 1600000
#define SLOPE  0.2f
#define EPSV   1e-16f

// ------------------------- scratch (static device) --------------------------
__device__ unsigned short g_csr[NEDGES];        // 3.2 MB
__device__ __half2        g_a1[NNODES * 8];     // (as,ad) per head, 1.6 MB
__device__ __half2        g_hin[NNODES * 32];   // hin fp16 [N,64], 6.4 MB
__device__ float          g_as2[NNODES];        // 0.2 MB
__device__ float          g_ad2[NNODES];        // 0.2 MB
__device__ int            g_row_ptr[NNODES + 1];
__device__ int            g_deg[NNODES];
__device__ int            g_pos[NNODES];
__device__ int            g_bsum[64];
__device__ int            g_boff[64];
__device__ float          g_vs[64];
__device__ float          g_vd[64];

__device__ __forceinline__ float lrelu(float v) { return fmaxf(v, SLOPE * v); }

// ------------------------------ CSR build -----------------------------------
__global__ void __launch_bounds__(256) k_init_deg(int n) {
    int i = blockIdx.x * blockDim.x + threadIdx.x;
    if (i < n) g_deg[i] = 0;
}

__global__ void __launch_bounds__(256) k_count(const int* __restrict__ dst, int n) {
    int e = blockIdx.x * blockDim.x + threadIdx.x;
    if (e < n) atomicAdd(&g_deg[dst[e]], 1);
}

#define SCAN_B 1024
__global__ void __launch_bounds__(SCAN_B) k_scan_local(int n) {
    __shared__ int s[SCAN_B];
    int tid = threadIdx.x;
    int i = blockIdx.x * SCAN_B + tid;
    int v = (i < n) ? g_deg[i] : 0;
    s[tid] = v;
    __syncthreads();
#pragma unroll
    for (int off = 1; off < SCAN_B; off <<= 1) {
        int t = (tid >= off) ? s[tid - off] : 0;
        __syncthreads();
        s[tid] += t;
        __syncthreads();
    }
    if (i < n) g_row_ptr[i] = s[tid] - v;
    if (tid == SCAN_B - 1) g_bsum[blockIdx.x] = s[tid];
}

__global__ void __launch_bounds__(64) k_scan_block(int nblk) {
    __shared__ int s[64];
    int i = threadIdx.x;
    int v = (i < nblk) ? g_bsum[i] : 0;
    s[i] = v;
    __syncthreads();
#pragma unroll
    for (int off = 1; off < 64; off <<= 1) {
        int t = (i >= off) ? s[i - off] : 0;
        __syncthreads();
        s[i] += t;
        __syncthreads();
    }
    if (i < nblk) g_boff[i] = s[i] - v;
}

__global__ void __launch_bounds__(SCAN_B) k_scan_add(int n) {
    int tid = threadIdx.x;
    int i = blockIdx.x * SCAN_B + tid;
    if (i < n) {
        int r = g_row_ptr[i] + g_boff[blockIdx.x];
        g_row_ptr[i] = r;
        g_pos[i] = r;
    }
    if (i == 0) g_row_ptr[NNODES] = NEDGES;
}

__global__ void __launch_bounds__(256) k_scatter(const int* __restrict__ src,
                                                 const int* __restrict__ dst, int n) {
    int e = blockIdx.x * blockDim.x + threadIdx.x;
    if (e < n) {
        int d = dst[e];
        int p = atomicAdd(&g_pos[d], 1);
        g_csr[p] = (unsigned short)src[e];
    }
}

// --------------------- GEMM1 + fused att1 epilogue ---------------------------
// C(half2)[M,32] = fp16(x @ W1); g_a1[row][head] = (h.as, h.ad) from fp32 accs.
__global__ void __launch_bounds__(256) k_gemm1(const float* __restrict__ A,
                                               const float* __restrict__ B,
                                               const float* __restrict__ att_src,
                                               const float* __restrict__ att_dst,
                                               __half2* __restrict__ C, int M) {
    const int block_row = blockIdx.x * 128;
    if (block_row >= M) return;
    __shared__ float xs[128][17];
    __shared__ float ws[16][64];
    __shared__ float ss[64], sd[64];
    const int tid = threadIdx.x;
    if (tid < 64) { ss[tid] = att_src[tid]; sd[tid] = att_dst[tid]; }
    const int colbase = (tid & 15) * 4;
    const int rowbase = tid >> 4;
    float acc[8][4];
#pragma unroll
    for (int i = 0; i < 8; i++)
#pragma unroll
        for (int j = 0; j < 4; j++) acc[i][j] = 0.f;

    for (int k0 = 0; k0 < 256; k0 += 16) {
#pragma unroll
        for (int it = 0; it < 2; it++) {
            int f4 = tid + it * 256;
            int r = f4 >> 2;
            int c = (f4 & 3) * 4;
            int gr = block_row + r;
            float4 v = make_float4(0.f, 0.f, 0.f, 0.f);
            if (gr < M) v = *(const float4*)(A + (size_t)gr * 256 + k0 + c);
            xs[r][c + 0] = v.x; xs[r][c + 1] = v.y;
            xs[r][c + 2] = v.z; xs[r][c + 3] = v.w;
        }
        {
            int r = tid >> 4;
            int c = (tid & 15) * 4;
            *(float4*)&ws[r][c] = *(const float4*)(B + (size_t)(k0 + r) * 64 + c);
        }
        __syncthreads();
#pragma unroll
        for (int kk = 0; kk < 16; kk++) {
            float b0 = ws[kk][colbase + 0];
            float b1 = ws[kk][colbase + 1];
            float b2 = ws[kk][colbase + 2];
            float b3 = ws[kk][colbase + 3];
#pragma unroll
            for (int i = 0; i < 8; i++) {
                float a = xs[rowbase + i * 16][kk];
                acc[i][0] += a * b0;
                acc[i][1] += a * b1;
                acc[i][2] += a * b2;
                acc[i][3] += a * b3;
            }
        }
        __syncthreads();
    }

    // store fp16 h1 + fused attention dots (pair tid/tid+1 covers one head)
    const float s0 = ss[colbase], s1 = ss[colbase + 1], s2 = ss[colbase + 2], s3 = ss[colbase + 3];
    const float d0 = sd[colbase], d1 = sd[colbase + 1], d2 = sd[colbase + 2], d3 = sd[colbase + 3];
    const int head = colbase >> 3;
#pragma unroll
    for (int i = 0; i < 8; i++) {
        int gr = block_row + rowbase + i * 16;
        float asp = acc[i][0] * s0 + acc[i][1] * s1 + acc[i][2] * s2 + acc[i][3] * s3;
        float adp = acc[i][0] * d0 + acc[i][1] * d1 + acc[i][2] * d2 + acc[i][3] * d3;
        asp += __shfl_down_sync(0xffffffffu, asp, 1);
        adp += __shfl_down_sync(0xffffffffu, adp, 1);
        if (gr < M) {
            C[(size_t)gr * 32 + (colbase >> 1)]     = __floats2half2_rn(acc[i][0], acc[i][1]);
            C[(size_t)gr * 32 + (colbase >> 1) + 1] = __floats2half2_rn(acc[i][2], acc[i][3]);
            if ((tid & 1) == 0)
                g_a1[(size_t)gr * 8 + head] = __floats2half2_rn(asp, adp);
        }
    }
}

// ---------------- vs = W2 @ att_src2, vd = W2 @ att_dst2 --------------------
__global__ void __launch_bounds__(64) k_vs(const float* __restrict__ W2,
                                           const float* __restrict__ att_src2,
                                           const float* __restrict__ att_dst2) {
    int k = threadIdx.x;
    float vs = 0.f, vd = 0.f;
    for (int j = 0; j < 64; j++) {
        float w = W2[k * 64 + j];
        vs += w * att_src2[j];
        vd += w * att_dst2[j];
    }
    g_vs[k] = vs;
    g_vd[k] = vd;
}

// ------- layer 1: ONE-pass softmax-agg + ELU + fused layer-2 att dots -------
// warp per node; lane owns features 2*lane, 2*lane+1 (head = lane>>2).
// h1 is fp16 half2 [N,32] (in d_out). Unrolled x4 for MLP.
__global__ void __launch_bounds__(256) k_edge1(const __half2* __restrict__ h1,
                                               const float* __restrict__ b1, int n) {
    int wid = (blockIdx.x * blockDim.x + threadIdx.x) >> 5;
    int lane = threadIdx.x & 31;
    if (wid >= n) return;
    const int d = wid;
    const int beg = g_row_ptr[d];
    const int end = g_row_ptr[d + 1];
    const int h0 = lane >> 2;
    const int f0 = 2 * lane;

    float2 pd = __half22float2(g_a1[(size_t)d * 8 + h0]);
    const float ad_h = pd.y;
    const float aself = lrelu(pd.x + ad_h);

    float acc0 = 0.f, acc1 = 0.f, sden = 0.f;
    int e = beg;
    for (; e + 4 <= end; e += 4) {
        int s0 = g_csr[e], s1 = g_csr[e + 1], s2 = g_csr[e + 2], s3 = g_csr[e + 3];
        float2 pa0 = __half22float2(g_a1[(size_t)s0 * 8 + h0]);
        float2 pa1 = __half22float2(g_a1[(size_t)s1 * 8 + h0]);
        float2 pa2 = __half22float2(g_a1[(size_t)s2 * 8 + h0]);
        float2 pa3 = __half22float2(g_a1[(size_t)s3 * 8 + h0]);
        float2 hv0 = __half22float2(h1[(size_t)s0 * 32 + lane]);
        float2 hv1 = __half22float2(h1[(size_t)s1 * 32 + lane]);
        float2 hv2 = __half22float2(h1[(size_t)s2 * 32 + lane]);
        float2 hv3 = __half22float2(h1[(size_t)s3 * 32 + lane]);
        float w0 = __expf(lrelu(pa0.x + ad_h));
        float w1 = __expf(lrelu(pa1.x + ad_h));
        float w2 = __expf(lrelu(pa2.x + ad_h));
        float w3 = __expf(lrelu(pa3.x + ad_h));
        sden += (w0 + w1) + (w2 + w3);
        acc0 += hv0.x * w0 + hv1.x * w1 + hv2.x * w2 + hv3.x * w3;
        acc1 += hv0.y * w0 + hv1.y * w1 + hv2.y * w2 + hv3.y * w3;
    }
    for (; e < end; e++) {
        int s = g_csr[e];
        float2 pa = __half22float2(g_a1[(size_t)s * 8 + h0]);
        float w = __expf(lrelu(pa.x + ad_h));
        sden += w;
        float2 hv = __half22float2(h1[(size_t)s * 32 + lane]);
        acc0 += hv.x * w;
        acc1 += hv.y * w;
    }
    {   // self loop
        float w = __expf(aself);
        sden += w;
        float2 hv = __half22float2(h1[(size_t)d * 32 + lane]);
        acc0 += hv.x * w;
        acc1 += hv.y * w;
    }
    float rinv = 1.f / (sden + EPSV);
    float2 bb = *(const float2*)(b1 + f0);
    float v0 = acc0 * rinv + bb.x;
    float v1 = acc1 * rinv + bb.y;
    v0 = (v0 > 0.f) ? v0 : (__expf(v0) - 1.f);   // ELU
    v1 = (v1 > 0.f) ? v1 : (__expf(v1) - 1.f);
    g_hin[(size_t)d * 32 + lane] = __floats2half2_rn(v0, v1);

    // fused layer-2 attention dots
    float ps = v0 * g_vs[f0] + v1 * g_vs[f0 + 1];
    float pdd = v0 * g_vd[f0] + v1 * g_vd[f0 + 1];
#pragma unroll
    for (int off = 16; off; off >>= 1) {
        ps  += __shfl_xor_sync(0xffffffffu, ps, off);
        pdd += __shfl_xor_sync(0xffffffffu, pdd, off);
    }
    if (lane == 0) {
        g_as2[d] = ps;
        g_ad2[d] = pdd;
    }
}

// -- layer 2: ONE-pass softmax-agg over hin, fused @W2 + b2 + log_softmax ----
__global__ void __launch_bounds__(256) k_edge2(const float* __restrict__ W2,
                                               const float* __restrict__ b2,
                                               float* __restrict__ out, int n) {
    __shared__ float2 W2s[64 * 32];
    __shared__ float  b2s[64];
    __shared__ float  sagg[8][64];
    int tid = threadIdx.x;
    {
        const float2* w2v = (const float2*)W2;
#pragma unroll
        for (int it = 0; it < 8; it++) W2s[tid + it * 256] = w2v[tid + it * 256];
        if (tid < 64) b2s[tid] = b2[tid];
    }
    __syncthreads();

    int wid = (blockIdx.x * blockDim.x + tid) >> 5;
    int wloc = (tid >> 5);
    int lane = tid & 31;
    if (wid >= n) return;
    const int d = wid;
    const int beg = g_row_ptr[d];
    const int end = g_row_ptr[d + 1];
    const float ad2 = g_ad2[d];
    const float aself = lrelu(g_as2[d] + ad2);

    float acc0 = 0.f, acc1 = 0.f, sden = 0.f;
    int e = beg;
    for (; e + 4 <= end; e += 4) {
        int s0 = g_csr[e], s1 = g_csr[e + 1], s2 = g_csr[e + 2], s3 = g_csr[e + 3];
        float a0 = g_as2[s0], a1 = g_as2[s1], a2 = g_as2[s2], a3 = g_as2[s3];
        float2 f0v = __half22float2(g_hin[(size_t)s0 * 32 + lane]);
        float2 f1v = __half22float2(g_hin[(size_t)s1 * 32 + lane]);
        float2 f2v = __half22float2(g_hin[(size_t)s2 * 32 + lane]);
        float2 f3v = __half22float2(g_hin[(size_t)s3 * 32 + lane]);
        float w0 = __expf(lrelu(a0 + ad2));
        float w1 = __expf(lrelu(a1 + ad2));
        float w2 = __expf(lrelu(a2 + ad2));
        float w3 = __expf(lrelu(a3 + ad2));
        sden += (w0 + w1) + (w2 + w3);
        acc0 += f0v.x * w0 + f1v.x * w1 + f2v.x * w2 + f3v.x * w3;
        acc1 += f0v.y * w0 + f1v.y * w1 + f2v.y * w2 + f3v.y * w3;
    }
    for (; e < end; e++) {
        int s = g_csr[e];
        float w = __expf(lrelu(g_as2[s] + ad2));
        sden += w;
        float2 f = __half22float2(g_hin[(size_t)s * 32 + lane]);
        acc0 += f.x * w;
        acc1 += f.y * w;
    }
    {
        float w = __expf(aself);
        sden += w;
        float2 f = __half22float2(g_hin[(size_t)d * 32 + lane]);
        acc0 += f.x * w;
        acc1 += f.y * w;
    }
    float rinv = 1.f / (sden + EPSV);
    acc0 *= rinv;
    acc1 *= rinv;

    sagg[wloc][2 * lane]     = acc0;
    sagg[wloc][2 * lane + 1] = acc1;
    __syncwarp();
    float o0 = b2s[2 * lane];
    float o1 = b2s[2 * lane + 1];
#pragma unroll
    for (int k = 0; k < 64; k++) {
        float a = sagg[wloc][k];
        float2 w2 = W2s[k * 32 + lane];
        o0 += a * w2.x;
        o1 += a * w2.y;
    }

    float mx = fmaxf(o0, o1);
#pragma unroll
    for (int off = 16; off; off >>= 1)
        mx = fmaxf(mx, __shfl_xor_sync(0xffffffffu, mx, off));
    float se = __expf(o0 - mx) + __expf(o1 - mx);
#pragma unroll
    for (int off = 16; off; off >>= 1)
        se += __shfl_xor_sync(0xffffffffu, se, off);
    float l = mx + logf(se);
    float2* out2 = (float2*)(out + (size_t)d * 64);
    out2[lane] = make_float2(o0 - l, o1 - l);
}

// ------------------------------ launcher ------------------------------------
extern "C" void kernel_launch(void* const* d_in, const int* in_sizes, int n_in,
                              void* d_out, int out_size) {
    const float* x        = (const float*)d_in[0];
    const int*   ei       = (const int*)d_in[1];
    const float* W1       = (const float*)d_in[2];
    const float* att_src1 = (const float*)d_in[3];
    const float* att_dst1 = (const float*)d_in[4];
    const float* b1       = (const float*)d_in[5];
    const float* W2       = (const float*)d_in[6];
    const float* att_src2 = (const float*)d_in[7];
    const float* att_dst2 = (const float*)d_in[8];
    const float* b2       = (const float*)d_in[9];
    float* out = (float*)d_out;

    const int* src = ei;
    const int* dst = ei + NEDGES;

    const int nblk_scan = (NNODES + SCAN_B - 1) / SCAN_B;   // 49

    // CSR build
    k_init_deg<<<(NNODES + 255) / 256, 256>>>(NNODES);
    k_count<<<(NEDGES + 255) / 256, 256>>>(dst, NEDGES);
    k_scan_local<<<nblk_scan, SCAN_B>>>(NNODES);
    k_scan_block<<<1, 64>>>(nblk_scan);
    k_scan_add<<<nblk_scan, SCAN_B>>>(NNODES);
    k_scatter<<<(NEDGES + 255) / 256, 256>>>(src, dst, NEDGES);

    // layer 1: h1(fp16) -> d_out, att1 dots fused -> g_a1
    k_gemm1<<<(NNODES + 127) / 128, 256>>>(x, W1, att_src1, att_dst1,
                                           (__half2*)out, NNODES);
    k_vs<<<1, 64>>>(W2, att_src2, att_dst2);
    k_edge1<<<(NNODES * 32 + 255) / 256, 256>>>((const __half2*)out, b1, NNODES);

    // layer 2 (no GEMM2, no att2 kernel: both fused)
    k_edge2<<<(NNODES * 32 + 255) / 256, 256>>>(W2, b2, out, NNODES);
}

// round 14
// speedup vs baseline: 1.5214x; 1.1669x over previous
#include <cuda_runtime.h>
#include <cuda_fp16.h>
#include <mma.h>

using namespace nvcuda;

// ---------------------------------------------------------------------------
// GAT (2-layer, PyG-style) on B200 (sm_100a). Pristine module form; total
// __device__ data ~12.2 MB. Layer-2 GEMM folded through the segment-sum.
//
// R14 vs R13 (248 us): gemm1 now uses wmma fp16 tensor cores (fp32 accum),
// converting x/W1 to fp16 in the smem staging path. Fused att1 epilogue kept
// (reads fp32 C tile in smem). Everything else unchanged.
//
// Pipeline:
//   1) CSR build over dst (int atomics; src as uint16)
//   2) gemm1(wmma): h1 = x @ W1 -> fp16 in d_out, fused att1 dots -> g_a1
//   3) vs/vd: W2 @ att2 vectors -> g_vs/g_vd
//   4) edge1: ONE-pass softmax-agg + b1 + ELU -> g_hin (fp16),
//             fused as2/ad2 = hin.(vs/vd) -> g_as2/g_ad2
//   5) edge2: ONE-pass softmax-agg over hin, fused @W2 + b2 + log_softmax
//             -> d_out (h1 dead)
// Self-loops handled analytically. Zero local memory in every kernel.
// ---------------------------------------------------------------------------

#define NNODES 50000
#define NEDGES 1600000
#define SLOPE  0.2f
#define EPSV   1e-16f

// ------------------------- scratch (static device) --------------------------
__device__ unsigned short g_csr[NEDGES];        // 3.2 MB
__device__ __half2        g_a1[NNODES * 8];     // (as,ad) per head, 1.6 MB
__device__ __half2        g_hin[NNODES * 32];   // hin fp16 [N,64], 6.4 MB
__device__ float          g_as2[NNODES];        // 0.2 MB
__device__ float          g_ad2[NNODES];        // 0.2 MB
__device__ int            g_row_ptr[NNODES + 1];
__device__ int            g_deg[NNODES];
__device__ int            g_pos[NNODES];
__device__ int            g_bsum[64];
__device__ int            g_boff[64];
__device__ float          g_vs[64];
__device__ float          g_vd[64];

__device__ __forceinline__ float lrelu(float v) { return fmaxf(v, SLOPE * v); }

// ------------------------------ CSR build -----------------------------------
__global__ void __launch_bounds__(256) k_init_deg(int n) {
    int i = blockIdx.x * blockDim.x + threadIdx.x;
    if (i < n) g_deg[i] = 0;
}

__global__ void __launch_bounds__(256) k_count(const int* __restrict__ dst, int n) {
    int e = blockIdx.x * blockDim.x + threadIdx.x;
    if (e < n) atomicAdd(&g_deg[dst[e]], 1);
}

#define SCAN_B 1024
__global__ void __launch_bounds__(SCAN_B) k_scan_local(int n) {
    __shared__ int s[SCAN_B];
    int tid = threadIdx.x;
    int i = blockIdx.x * SCAN_B + tid;
    int v = (i < n) ? g_deg[i] : 0;
    s[tid] = v;
    __syncthreads();
#pragma unroll
    for (int off = 1; off < SCAN_B; off <<= 1) {
        int t = (tid >= off) ? s[tid - off] : 0;
        __syncthreads();
        s[tid] += t;
        __syncthreads();
    }
    if (i < n) g_row_ptr[i] = s[tid] - v;
    if (tid == SCAN_B - 1) g_bsum[blockIdx.x] = s[tid];
}

__global__ void __launch_bounds__(64) k_scan_block(int nblk) {
    __shared__ int s[64];
    int i = threadIdx.x;
    int v = (i < nblk) ? g_bsum[i] : 0;
    s[i] = v;
    __syncthreads();
#pragma unroll
    for (int off = 1; off < 64; off <<= 1) {
        int t = (i >= off) ? s[i - off] : 0;
        __syncthreads();
        s[i] += t;
        __syncthreads();
    }
    if (i < nblk) g_boff[i] = s[i] - v;
}

__global__ void __launch_bounds__(SCAN_B) k_scan_add(int n) {
    int tid = threadIdx.x;
    int i = blockIdx.x * SCAN_B + tid;
    if (i < n) {
        int r = g_row_ptr[i] + g_boff[blockIdx.x];
        g_row_ptr[i] = r;
        g_pos[i] = r;
    }
    if (i == 0) g_row_ptr[NNODES] = NEDGES;
}

__global__ void __launch_bounds__(256) k_scatter(const int* __restrict__ src,
                                                 const int* __restrict__ dst, int n) {
    int e = blockIdx.x * blockDim.x + threadIdx.x;
    if (e < n) {
        int d = dst[e];
        int p = atomicAdd(&g_pos[d], 1);
        g_csr[p] = (unsigned short)src[e];
    }
}

// --------------- GEMM1 (wmma fp16 tensor cores) + fused att1 -----------------
// h1[M,64] = x[M,256] @ W1[256,64]; fp16 inputs, fp32 accum.
// Tile 128x64, BK=32, 8 warps as 4(M)x2(N), each warp 32x32 (2x2 frags).
// C tile staged in smem (union with A/B staging), epilogue: fp16 h1 + att dots.
struct GemmAB {
    __half As[128][40];     // 128x32 + pad8
    __half Bs[32][72];      // 32x64 + pad8
};
union GemmSmem {
    GemmAB ab;
    float  Cs[128][68];     // 128x64 + pad4
};

__global__ void __launch_bounds__(256) k_gemm1(const float* __restrict__ A,
                                               const float* __restrict__ B,
                                               const float* __restrict__ att_src,
                                               const float* __restrict__ att_dst,
                                               __half2* __restrict__ C, int M) {
    const int block_row = blockIdx.x * 128;
    if (block_row >= M) return;
    __shared__ GemmSmem sm;
    __shared__ float ss[64], sd[64];
    const int tid = threadIdx.x;
    if (tid < 64) { ss[tid] = att_src[tid]; sd[tid] = att_dst[tid]; }

    const int wid = tid >> 5;
    const int warp_m = wid & 3;          // 0..3 -> rows warp_m*32
    const int warp_n = wid >> 2;         // 0..1 -> cols warp_n*32

    wmma::fragment<wmma::accumulator, 16, 16, 16, float> acc[2][2];
#pragma unroll
    for (int i = 0; i < 2; i++)
#pragma unroll
        for (int j = 0; j < 2; j++) wmma::fill_fragment(acc[i][j], 0.f);

    for (int k0 = 0; k0 < 256; k0 += 32) {
        // stage A tile 128x32 (fp32 -> fp16): 1024 float4, 4 per thread
#pragma unroll
        for (int it = 0; it < 4; it++) {
            int f4 = it * 256 + tid;
            int r = f4 >> 3;             // 8 float4 per row
            int c4 = (f4 & 7) * 4;
            int gr = block_row + r;
            float4 v = make_float4(0.f, 0.f, 0.f, 0.f);
            if (gr < M) v = *(const float4*)(A + (size_t)gr * 256 + k0 + c4);
            sm.ab.As[r][c4 + 0] = __float2half_rn(v.x);
            sm.ab.As[r][c4 + 1] = __float2half_rn(v.y);
            sm.ab.As[r][c4 + 2] = __float2half_rn(v.z);
            sm.ab.As[r][c4 + 3] = __float2half_rn(v.w);
        }
        // stage B tile 32x64: 512 float4, 2 per thread
#pragma unroll
        for (int it = 0; it < 2; it++) {
            int f4 = it * 256 + tid;
            int r = f4 >> 4;             // 16 float4 per row
            int c4 = (f4 & 15) * 4;
            float4 v = *(const float4*)(B + (size_t)(k0 + r) * 64 + c4);
            sm.ab.Bs[r][c4 + 0] = __float2half_rn(v.x);
            sm.ab.Bs[r][c4 + 1] = __float2half_rn(v.y);
            sm.ab.Bs[r][c4 + 2] = __float2half_rn(v.z);
            sm.ab.Bs[r][c4 + 3] = __float2half_rn(v.w);
        }
        __syncthreads();
#pragma unroll
        for (int kf = 0; kf < 2; kf++) {
            wmma::fragment<wmma::matrix_a, 16, 16, 16, __half, wmma::row_major> a_frag[2];
            wmma::fragment<wmma::matrix_b, 16, 16, 16, __half, wmma::row_major> b_frag[2];
#pragma unroll
            for (int fm = 0; fm < 2; fm++)
                wmma::load_matrix_sync(a_frag[fm],
                    &sm.ab.As[warp_m * 32 + fm * 16][kf * 16], 40);
#pragma unroll
            for (int fn = 0; fn < 2; fn++)
                wmma::load_matrix_sync(b_frag[fn],
                    &sm.ab.Bs[kf * 16][warp_n * 32 + fn * 16], 72);
#pragma unroll
            for (int fm = 0; fm < 2; fm++)
#pragma unroll
                for (int fn = 0; fn < 2; fn++)
                    wmma::mma_sync(acc[fm][fn], a_frag[fm], b_frag[fn], acc[fm][fn]);
        }
        __syncthreads();
    }

    // stage C tile (fp32) to smem (aliases As/Bs; all reads done)
#pragma unroll
    for (int fm = 0; fm < 2; fm++)
#pragma unroll
        for (int fn = 0; fn < 2; fn++)
            wmma::store_matrix_sync(&sm.Cs[warp_m * 32 + fm * 16][warp_n * 32 + fn * 16],
                                    acc[fm][fn], 68, wmma::mem_row_major);
    __syncthreads();

    // epilogue: thread t < 128 owns row t
    if (tid < 128) {
        int gr = block_row + tid;
        if (gr < M) {
            const float* row = sm.Cs[tid];
#pragma unroll
            for (int c = 0; c < 32; c++)
                C[(size_t)gr * 32 + c] = __floats2half2_rn(row[2 * c], row[2 * c + 1]);
#pragma unroll
            for (int h = 0; h < 8; h++) {
                float as = 0.f, ad = 0.f;
#pragma unroll
                for (int j = 0; j < 8; j++) {
                    float v = row[h * 8 + j];
                    as += v * ss[h * 8 + j];
                    ad += v * sd[h * 8 + j];
                }
                g_a1[(size_t)gr * 8 + h] = __floats2half2_rn(as, ad);
            }
        }
    }
}

// ---------------- vs = W2 @ att_src2, vd = W2 @ att_dst2 --------------------
__global__ void __launch_bounds__(64) k_vs(const float* __restrict__ W2,
                                           const float* __restrict__ att_src2,
                                           const float* __restrict__ att_dst2) {
    int k = threadIdx.x;
    float vs = 0.f, vd = 0.f;
    for (int j = 0; j < 64; j++) {
        float w = W2[k * 64 + j];
        vs += w * att_src2[j];
        vd += w * att_dst2[j];
    }
    g_vs[k] = vs;
    g_vd[k] = vd;
}

// ------- layer 1: ONE-pass softmax-agg + ELU + fused layer-2 att dots -------
__global__ void __launch_bounds__(256) k_edge1(const __half2* __restrict__ h1,
                                               const float* __restrict__ b1, int n) {
    int wid = (blockIdx.x * blockDim.x + threadIdx.x) >> 5;
    int lane = threadIdx.x & 31;
    if (wid >= n) return;
    const int d = wid;
    const int beg = g_row_ptr[d];
    const int end = g_row_ptr[d + 1];
    const int h0 = lane >> 2;
    const int f0 = 2 * lane;

    float2 pd = __half22float2(g_a1[(size_t)d * 8 + h0]);
    const float ad_h = pd.y;
    const float aself = lrelu(pd.x + ad_h);

    float acc0 = 0.f, acc1 = 0.f, sden = 0.f;
    int e = beg;
    for (; e + 4 <= end; e += 4) {
        int s0 = g_csr[e], s1 = g_csr[e + 1], s2 = g_csr[e + 2], s3 = g_csr[e + 3];
        float2 pa0 = __half22float2(g_a1[(size_t)s0 * 8 + h0]);
        float2 pa1 = __half22float2(g_a1[(size_t)s1 * 8 + h0]);
        float2 pa2 = __half22float2(g_a1[(size_t)s2 * 8 + h0]);
        float2 pa3 = __half22float2(g_a1[(size_t)s3 * 8 + h0]);
        float2 hv0 = __half22float2(h1[(size_t)s0 * 32 + lane]);
        float2 hv1 = __half22float2(h1[(size_t)s1 * 32 + lane]);
        float2 hv2 = __half22float2(h1[(size_t)s2 * 32 + lane]);
        float2 hv3 = __half22float2(h1[(size_t)s3 * 32 + lane]);
        float w0 = __expf(lrelu(pa0.x + ad_h));
        float w1 = __expf(lrelu(pa1.x + ad_h));
        float w2 = __expf(lrelu(pa2.x + ad_h));
        float w3 = __expf(lrelu(pa3.x + ad_h));
        sden += (w0 + w1) + (w2 + w3);
        acc0 += hv0.x * w0 + hv1.x * w1 + hv2.x * w2 + hv3.x * w3;
        acc1 += hv0.y * w0 + hv1.y * w1 + hv2.y * w2 + hv3.y * w3;
    }
    for (; e < end; e++) {
        int s = g_csr[e];
        float2 pa = __half22float2(g_a1[(size_t)s * 8 + h0]);
        float w = __expf(lrelu(pa.x + ad_h));
        sden += w;
        float2 hv = __half22float2(h1[(size_t)s * 32 + lane]);
        acc0 += hv.x * w;
        acc1 += hv.y * w;
    }
    {   // self loop
        float w = __expf(aself);
        sden += w;
        float2 hv = __half22float2(h1[(size_t)d * 32 + lane]);
        acc0 += hv.x * w;
        acc1 += hv.y * w;
    }
    float rinv = 1.f / (sden + EPSV);
    float2 bb = *(const float2*)(b1 + f0);
    float v0 = acc0 * rinv + bb.x;
    float v1 = acc1 * rinv + bb.y;
    v0 = (v0 > 0.f) ? v0 : (__expf(v0) - 1.f);   // ELU
    v1 = (v1 > 0.f) ? v1 : (__expf(v1) - 1.f);
    g_hin[(size_t)d * 32 + lane] = __floats2half2_rn(v0, v1);

    float ps = v0 * g_vs[f0] + v1 * g_vs[f0 + 1];
    float pdd = v0 * g_vd[f0] + v1 * g_vd[f0 + 1];
#pragma unroll
    for (int off = 16; off; off >>= 1) {
        ps  += __shfl_xor_sync(0xffffffffu, ps, off);
        pdd += __shfl_xor_sync(0xffffffffu, pdd, off);
    }
    if (lane == 0) {
        g_as2[d] = ps;
        g_ad2[d] = pdd;
    }
}

// -- layer 2: ONE-pass softmax-agg over hin, fused @W2 + b2 + log_softmax ----
__global__ void __launch_bounds__(256) k_edge2(const float* __restrict__ W2,
                                               const float* __restrict__ b2,
                                               float* __restrict__ out, int n) {
    __shared__ float2 W2s[64 * 32];
    __shared__ float  b2s[64];
    __shared__ float  sagg[8][64];
    int tid = threadIdx.x;
    {
        const float2* w2v = (const float2*)W2;
#pragma unroll
        for (int it = 0; it < 8; it++) W2s[tid + it * 256] = w2v[tid + it * 256];
        if (tid < 64) b2s[tid] = b2[tid];
    }
    __syncthreads();

    int wid = (blockIdx.x * blockDim.x + tid) >> 5;
    int wloc = (tid >> 5);
    int lane = tid & 31;
    if (wid >= n) return;
    const int d = wid;
    const int beg = g_row_ptr[d];
    const int end = g_row_ptr[d + 1];
    const float ad2 = g_ad2[d];
    const float aself = lrelu(g_as2[d] + ad2);

    float acc0 = 0.f, acc1 = 0.f, sden = 0.f;
    int e = beg;
    for (; e + 4 <= end; e += 4) {
        int s0 = g_csr[e], s1 = g_csr[e + 1], s2 = g_csr[e + 2], s3 = g_csr[e + 3];
        float a0 = g_as2[s0], a1 = g_as2[s1], a2 = g_as2[s2], a3 = g_as2[s3];
        float2 f0v = __half22float2(g_hin[(size_t)s0 * 32 + lane]);
        float2 f1v = __half22float2(g_hin[(size_t)s1 * 32 + lane]);
        float2 f2v = __half22float2(g_hin[(size_t)s2 * 32 + lane]);
        float2 f3v = __half22float2(g_hin[(size_t)s3 * 32 + lane]);
        float w0 = __expf(lrelu(a0 + ad2));
        float w1 = __expf(lrelu(a1 + ad2));
        float w2 = __expf(lrelu(a2 + ad2));
        float w3 = __expf(lrelu(a3 + ad2));
        sden += (w0 + w1) + (w2 + w3);
        acc0 += f0v.x * w0 + f1v.x * w1 + f2v.x * w2 + f3v.x * w3;
        acc1 += f0v.y * w0 + f1v.y * w1 + f2v.y * w2 + f3v.y * w3;
    }
    for (; e < end; e++) {
        int s = g_csr[e];
        float w = __expf(lrelu(g_as2[s] + ad2));
        sden += w;
        float2 f = __half22float2(g_hin[(size_t)s * 32 + lane]);
        acc0 += f.x * w;
        acc1 += f.y * w;
    }
    {
        float w = __expf(aself);
        sden += w;
        float2 f = __half22float2(g_hin[(size_t)d * 32 + lane]);
        acc0 += f.x * w;
        acc1 += f.y * w;
    }
    float rinv = 1.f / (sden + EPSV);
    acc0 *= rinv;
    acc1 *= rinv;

    sagg[wloc][2 * lane]     = acc0;
    sagg[wloc][2 * lane + 1] = acc1;
    __syncwarp();
    float o0 = b2s[2 * lane];
    float o1 = b2s[2 * lane + 1];
#pragma unroll
    for (int k = 0; k < 64; k++) {
        float a = sagg[wloc][k];
        float2 w2 = W2s[k * 32 + lane];
        o0 += a * w2.x;
        o1 += a * w2.y;
    }

    float mx = fmaxf(o0, o1);
#pragma unroll
    for (int off = 16; off; off >>= 1)
        mx = fmaxf(mx, __shfl_xor_sync(0xffffffffu, mx, off));
    float se = __expf(o0 - mx) + __expf(o1 - mx);
#pragma unroll
    for (int off = 16; off; off >>= 1)
        se += __shfl_xor_sync(0xffffffffu, se, off);
    float l = mx + logf(se);
    float2* out2 = (float2*)(out + (size_t)d * 64);
    out2[lane] = make_float2(o0 - l, o1 - l);
}

// ------------------------------ launcher ------------------------------------
extern "C" void kernel_launch(void* const* d_in, const int* in_sizes, int n_in,
                              void* d_out, int out_size) {
    const float* x        = (const float*)d_in[0];
    const int*   ei       = (const int*)d_in[1];
    const float* W1       = (const float*)d_in[2];
    const float* att_src1 = (const float*)d_in[3];
    const float* att_dst1 = (const float*)d_in[4];
    const float* b1       = (const float*)d_in[5];
    const float* W2       = (const float*)d_in[6];
    const float* att_src2 = (const float*)d_in[7];
    const float* att_dst2 = (const float*)d_in[8];
    const float* b2       = (const float*)d_in[9];
    float* out = (float*)d_out;

    const int* src = ei;
    const int* dst = ei + NEDGES;

    const int nblk_scan = (NNODES + SCAN_B - 1) / SCAN_B;   // 49

    // CSR build
    k_init_deg<<<(NNODES + 255) / 256, 256>>>(NNODES);
    k_count<<<(NEDGES + 255) / 256, 256>>>(dst, NEDGES);
    k_scan_local<<<nblk_scan, SCAN_B>>>(NNODES);
    k_scan_block<<<1, 64>>>(nblk_scan);
    k_scan_add<<<nblk_scan, SCAN_B>>>(NNODES);
    k_scatter<<<(NEDGES + 255) / 256, 256>>>(src, dst, NEDGES);

    // layer 1: h1(fp16) -> d_out, att1 dots fused -> g_a1
    k_gemm1<<<(NNODES + 127) / 128, 256>>>(x, W1, att_src1, att_dst1,
                                           (__half2*)out, NNODES);
    k_vs<<<1, 64>>>(W2, att_src2, att_dst2);
    k_edge1<<<(NNODES * 32 + 255) / 256, 256>>>((const __half2*)out, b1, NNODES);

    // layer 2 (no GEMM2, no att2 kernel: both fused)
    k_edge2<<<(NNODES * 32 + 255) / 256, 256>>>(W2, b2, out, NNODES);
}